// round 17
// baseline (speedup 1.0000x reference)
#include <cuda_runtime.h>
#include <cuda_bf16.h>
#include <cuda_fp16.h>
#include <math.h>
#include <stdint.h>

#define Vn 100000
#define Dn 256
#define Bn 512
#define Sn 20
#define Nn (Bn*Sn)      // 10240
#define En (8*Nn)       // 81920
#define DEGMAX 128
#define DCACHE 24
#define SHIFT 4.0f

// ---------------- scratch ----------------
__device__ float g_inorm[Vn];
__device__ float g_hv[Nn*Dn];
__device__ float g_h[Nn*Dn];
__device__ float g_f[Bn*Dn];
__device__ float g_mscal[Nn];
__device__ float g_srn[Bn*Dn];
__device__ float g_logphi[Bn*2];
__device__ double g_rowsum[Bn];
__device__ double g_msum[Bn];
__device__ int   g_mask_v[Bn*Sn];
__device__ float g_mask_l[Bn*Sn];
// CSR
__device__ int g_deg[Nn];
__device__ int g_off[Nn+1];
__device__ int g_pos[Nn];
__device__ int g_eidx[En];
// packed big-GEMM operands (fp16 single-term)
__device__ uint2 g_bp[(size_t)Vn*64];   // 51.2 MB
__device__ uint2 g_ap[Bn*64];           // 0.25 MB
// eagg path
__device__ uint4 g_hp[Nn*64];           // 10.5 MB
__device__ uint4 g_qp[Dn*64];           // 0.26 MB
__device__ float g_posq[Sn*Dn];
// fp16 staging for unshifted logits
__device__ __half g_lt[(size_t)Bn*Vn];  // 102.4 MB

// ---------------- helpers ----------------
__device__ __forceinline__ unsigned short hfr(float x){
    __half h = __float2half_rn(x);
    return *(unsigned short*)&h;
}
__device__ __forceinline__ unsigned short bfr(float x){
    __nv_bfloat16 h = __float2bfloat16(x);
    return *(unsigned short*)&h;
}
__device__ __forceinline__ float bff(unsigned short u){
    __nv_bfloat16 h = *(__nv_bfloat16*)&u;
    return __bfloat162float(h);
}
__device__ __forceinline__ unsigned smem_u32(const void* p){
    unsigned a;
    asm("{ .reg .u64 t; cvta.to.shared.u64 t, %1; cvt.u32.u64 %0, t; }" : "=r"(a) : "l"(p));
    return a;
}
__device__ __forceinline__ float tanha(float x){
    float y; asm("tanh.approx.f32 %0, %1;" : "=f"(y) : "f"(x)); return y;
}
__device__ __forceinline__ float exp2_pair_sum(float y0, float y1){
    unsigned p, e;
    asm("cvt.rn.f16x2.f32 %0, %1, %2;" : "=r"(p) : "f"(y1), "f"(y0));
    asm("ex2.approx.f16x2 %0, %1;" : "=r"(e) : "r"(p));
    __half2 he = *reinterpret_cast<__half2*>(&e);
    float2 fe = __half22float2(he);
    return fe.x + fe.y;
}

#define MMA_BF16(d, a0, a1, a2, a3, b0, b1) \
    asm volatile("mma.sync.aligned.m16n8k16.row.col.f32.bf16.bf16.f32 " \
        "{%0,%1,%2,%3}, {%4,%5,%6,%7}, {%8,%9}, {%0,%1,%2,%3};" \
        : "+f"((d)[0]), "+f"((d)[1]), "+f"((d)[2]), "+f"((d)[3]) \
        : "r"(a0), "r"(a1), "r"(a2), "r"(a3), "r"(b0), "r"(b1))
// fp16-accumulator variant: c/d are 2 packed f16x2 regs
#define MMA_F16ACC(c0, c1, a0, a1, a2, a3, b0, b1) \
    asm volatile("mma.sync.aligned.m16n8k16.row.col.f16.f16.f16.f16 " \
        "{%0,%1}, {%2,%3,%4,%5}, {%6,%7}, {%0,%1};" \
        : "+r"(c0), "+r"(c1) \
        : "r"(a0), "r"(a1), "r"(a2), "r"(a3), "r"(b0), "r"(b1))

__device__ __forceinline__ void cp16(unsigned dst, const void* src, int src_bytes){
    asm volatile("cp.async.cg.shared.global [%0], [%1], 16, %2;"
        :: "r"(dst), "l"(src), "r"(src_bytes) : "memory");
}
#define CP_COMMIT() asm volatile("cp.async.commit_group;" ::: "memory")
#define CP_WAIT2()  asm volatile("cp.async.wait_group 2;" ::: "memory")

// ---------------- K0: zero scratch ----------------
__global__ void k_zero(){
    int i = blockIdx.x*blockDim.x + threadIdx.x;
    if (i < Nn){ g_deg[i] = 0; g_mscal[i] = 0.f; }
    if (i < Bn){ g_rowsum[i]=0.0; g_msum[i]=0.0; }
}

// ---------------- CSR build ----------------
__global__ void k_count(const int* __restrict__ dst){
    int e = blockIdx.x*blockDim.x + threadIdx.x;
    if (e < En) atomicAdd(&g_deg[dst[e]], 1);
}
__global__ void k_scan(){
    __shared__ int warp_sums[32];
    int t = threadIdx.x;
    int base = t*10;
    int local[10]; int s = 0;
    #pragma unroll
    for (int i=0;i<10;i++){ local[i]=s; s += g_deg[base+i]; }
    int lane = t&31, w = t>>5;
    int v = s;
    #pragma unroll
    for (int o=1;o<32;o<<=1){ int u=__shfl_up_sync(0xffffffffu,v,o); if(lane>=o) v+=u; }
    if (lane==31) warp_sums[w]=v;
    __syncthreads();
    if (w==0){
        int x = warp_sums[lane];
        #pragma unroll
        for (int o=1;o<32;o<<=1){ int u=__shfl_up_sync(0xffffffffu,x,o); if(lane>=o) x+=u; }
        warp_sums[lane]=x;
    }
    __syncthreads();
    int excl = v - s + (w>0 ? warp_sums[w-1] : 0);
    #pragma unroll
    for (int i=0;i<10;i++){ g_off[base+i]=excl+local[i]; g_pos[base+i]=excl+local[i]; }
    if (t==1023) g_off[Nn]=En;
}
__global__ void k_scatter(const int* __restrict__ dst){
    int e = blockIdx.x*blockDim.x + threadIdx.x;
    if (e < En){
        int p = atomicAdd(&g_pos[dst[e]], 1);
        g_eidx[p] = e;
    }
}

// ---------------- fused: emb row norms + fp16 fragment pack ----------------
__global__ void __launch_bounds__(256) k_bpacknorm(const float* __restrict__ emb){
    __shared__ float rows[8][Dn];
    int w = threadIdx.x>>5, lane = threadIdx.x&31;
    int row = blockIdx.x*8 + w;
    const float4* p = (const float4*)(emb + (size_t)row*Dn);
    float4 a = p[lane*2], b = p[lane*2+1];
    float ss = a.x*a.x+a.y*a.y+a.z*a.z+a.w*a.w + b.x*b.x+b.y*b.y+b.z*b.z+b.w*b.w;
    #pragma unroll
    for (int o=16;o;o>>=1) ss += __shfl_xor_sync(0xffffffffu, ss, o);
    if (lane==0) g_inorm[row] = 1.f / fmaxf(sqrtf(ss), 1e-12f);
    *(float4*)&rows[w][lane*8]   = a;
    *(float4*)&rows[w][lane*8+4] = b;
    __syncwarp();
    #pragma unroll
    for (int rep=0; rep<2; rep++){
        int s = lane + rep*32;
        int c = s>>2, t = s&3;
        int k0 = c*16 + 2*t;
        unsigned short h0=hfr(rows[w][k0]),   h1=hfr(rows[w][k0+1]);
        unsigned short h2=hfr(rows[w][k0+8]), h3=hfr(rows[w][k0+9]);
        uint2 o;
        o.x = ((unsigned)h1<<16) | h0;
        o.y = ((unsigned)h3<<16) | h2;
        g_bp[(size_t)row*64 + s] = o;
    }
}

// ---------------- K_setup: hv gather + q_w^T pack + posq (merged) ----------------
__global__ void k_setup(const float* __restrict__ emb, const int* __restrict__ iid,
                        const float* __restrict__ q_w, const float* __restrict__ pos_emb){
    int bid = blockIdx.x;
    int tid = threadIdx.x;
    if (bid < (Nn*Dn)/256){
        int i = bid*256 + tid;
        int n = i>>8, k = i&255;
        int id = iid[n];
        g_hv[i] = emb[(size_t)id*Dn + k] * g_inorm[id];
    } else if (bid < (Nn*Dn)/256 + (Dn*64)/256){
        int id = (bid - (Nn*Dn)/256)*256 + tid;
        int n = id>>6, s = id&63;
        int c = s>>2, t = s&3;
        int k0 = c*16 + 2*t;
        float v0=q_w[(size_t)k0*Dn+n], v1=q_w[(size_t)(k0+1)*Dn+n];
        float v2=q_w[(size_t)(k0+8)*Dn+n], v3=q_w[(size_t)(k0+9)*Dn+n];
        unsigned short h0=bfr(v0), h1=bfr(v1), h2=bfr(v2), h3=bfr(v3);
        unsigned short l0=bfr(v0-bff(h0)), l1=bfr(v1-bff(h1)), l2=bfr(v2-bff(h2)), l3=bfr(v3-bff(h3));
        uint4 o;
        o.x = ((unsigned)h1<<16) | h0;
        o.y = ((unsigned)h3<<16) | h2;
        o.z = ((unsigned)l1<<16) | l0;
        o.w = ((unsigned)l3<<16) | l2;
        g_qp[n*64 + s] = o;
    } else {
        int p = bid - (Nn*Dn)/256 - (Dn*64)/256;
        int d = tid;
        float s = 0.f;
        const float* pe = pos_emb + (size_t)p*Dn;
        for (int k=0;k<Dn;k++)
            s += pe[k] * q_w[(size_t)(Dn+k)*Dn + d];
        g_posq[p*Dn + d] = s;
    }
}

// ---------------- K3: fused gather GAT + bf16 hi/lo pack ----------------
__global__ void __launch_bounds__(256) k_gat(const int* __restrict__ src, const int* __restrict__ dis,
                      const float* __restrict__ dis_emb,
                      const float* __restrict__ pi_w, const float* __restrict__ M_w){
    __shared__ float hd[Dn];
    __shared__ float se[DEGMAX];
    __shared__ int   ssrc[DEGMAX];
    __shared__ float cache[DCACHE][Dn];
    int d = blockIdx.x;
    int t = threadIdx.x;
    int beg = g_off[d], end = g_off[d+1];
    int deg = end - beg; if (deg > DEGMAX) deg = DEGMAX;
    float val = 0.f;
    if (deg > 0){
        hd[t] = g_hv[(size_t)d*Dn + t];
        __syncthreads();
        int warp = t>>5, lane = t&31;
        for (int slot=warp; slot<deg; slot+=8){
            int e = g_eidx[beg+slot];
            int s = src[e], di = dis[e];
            const float* hs = g_hv + (size_t)s*Dn;
            const float* he = dis_emb + (size_t)di*Dn;
            float e1 = 0.f, g = 0.f;
            bool cz = (slot < DCACHE);
            for (int k=lane;k<Dn;k+=32){
                float a = hs[k], b = hd[k], c = he[k];
                if (cz) cache[slot][k] = a;
                float p = a*b;
                e1 += p*c*pi_w[k];
                g  += p*M_w[k] + c*M_w[Dn+k];
            }
            #pragma unroll
            for (int o=16;o;o>>=1){
                e1 += __shfl_xor_sync(0xffffffffu, e1, o);
                g  += __shfl_xor_sync(0xffffffffu, g,  o);
            }
            if (lane==0){
                se[slot] = e1 * (1.f/(1.f+__expf(-g)));
                ssrc[slot] = s;
            }
        }
        __syncthreads();
        float mx = -3.4e38f;
        for (int i=0;i<deg;i++) mx = fmaxf(mx, se[i]);
        float acc = 0.f, asum = 0.f;
        for (int i=0;i<deg;i++){
            float a = __expf(se[i]-mx);
            asum += a;
            float hv = (i < DCACHE) ? cache[i][t] : g_hv[(size_t)ssrc[i]*Dn + t];
            acc += a * hv;
        }
        val = acc / asum;
        __syncthreads();
    }
    g_h[(size_t)d*Dn + t] = val;
    hd[t] = val;
    __syncthreads();
    if (t < 64){
        int s = t;
        int c = s>>2, tq = s&3;
        int k0 = c*16 + 2*tq;
        float v0=hd[k0], v1=hd[k0+1], v2=hd[k0+8], v3=hd[k0+9];
        unsigned short h0=bfr(v0), h1=bfr(v1), h2=bfr(v2), h3=bfr(v3);
        unsigned short l0=bfr(v0-bff(h0)), l1=bfr(v1-bff(h1)), l2=bfr(v2-bff(h2)), l3=bfr(v3-bff(h3));
        uint4 o;
        o.x = ((unsigned)h1<<16) | h0;
        o.y = ((unsigned)h3<<16) | h2;
        o.z = ((unsigned)l1<<16) | l0;
        o.w = ((unsigned)l3<<16) | l2;
        g_hp[d*64 + s] = o;
    }
}

// ---------------- K6: f = concat(h_t, last_feat) @ r_w ----------------
__global__ void k_f(const int* __restrict__ tid_, const int* __restrict__ last_idx,
                    const float* __restrict__ target_emb, const float* __restrict__ r_w){
    __shared__ float sin_[8][2*Dn];
    int b0 = blockIdx.x*8;
    int t = threadIdx.x;
    for (int idx=t; idx<8*2*Dn; idx+=256){
        int j = idx>>9, k = idx&511;
        int b = b0+j;
        float v = (k<Dn) ? target_emb[(size_t)tid_[b]*Dn + k]
                         : g_h[(size_t)last_idx[b]*Dn + (k-Dn)];
        sin_[j][k] = v;
    }
    __syncthreads();
    float acc[8] = {0,0,0,0,0,0,0,0};
    int d = t;
    for (int k=0;k<2*Dn;k++){
        float w = r_w[(size_t)k*Dn + d];
        #pragma unroll
        for (int j=0;j<8;j++) acc[j] += sin_[j][k]*w;
    }
    #pragma unroll
    for (int j=0;j<8;j++) g_f[(size_t)(b0+j)*Dn + d] = acc[j];
}

// ---------------- K7: eagg via bf16 3-term mma ----------------
__global__ void __launch_bounds__(256) k_eagg_mma(){
    int tid = threadIdx.x;
    int w = tid>>5, lane = tid&31;
    int g = lane>>2, t = lane&3;
    int wm = w>>1, wn = w&1;
    int m0 = blockIdx.x*128;
    int n0 = blockIdx.y*128;

    int ar0 = m0 + wm*32 + g;
    const uint4* aptr[2][2];
    #pragma unroll
    for (int mi=0;mi<2;mi++)
        #pragma unroll
        for (int rp=0;rp<2;rp++)
            aptr[mi][rp] = g_hp + (ar0 + mi*16 + rp*8)*64 + t;
    const uint4* bptr[8];
    #pragma unroll
    for (int ni=0;ni<8;ni++)
        bptr[ni] = g_qp + (n0 + wn*64 + ni*8 + g)*64 + t;

    float acc[2][8][4];
    #pragma unroll
    for (int mi=0;mi<2;mi++)
        #pragma unroll
        for (int ni=0;ni<8;ni++)
            #pragma unroll
            for (int q=0;q<4;q++) acc[mi][ni][q]=0.f;

    #pragma unroll 2
    for (int c=0; c<16; c++){
        int so = c*4;
        uint4 A0[2], A1[2];
        #pragma unroll
        for (int mi=0;mi<2;mi++){
            A0[mi] = __ldg(aptr[mi][0] + so);
            A1[mi] = __ldg(aptr[mi][1] + so);
        }
        #pragma unroll
        for (int ni=0;ni<8;ni++){
            uint4 b = __ldg(bptr[ni] + so);
            #pragma unroll
            for (int mi=0;mi<2;mi++){
                MMA_BF16(acc[mi][ni], A0[mi].x, A1[mi].x, A0[mi].y, A1[mi].y, b.x, b.y);
                MMA_BF16(acc[mi][ni], A0[mi].x, A1[mi].x, A0[mi].y, A1[mi].y, b.z, b.w);
                MMA_BF16(acc[mi][ni], A0[mi].z, A1[mi].z, A0[mi].w, A1[mi].w, b.x, b.y);
            }
        }
    }

    float rsum[2][2] = {{0.f,0.f},{0.f,0.f}};
    #pragma unroll
    for (int mi=0;mi<2;mi++){
        #pragma unroll
        for (int rp=0;rp<2;rp++){
            int r = ar0 + mi*16 + rp*8;
            int p = r % Sn, se = r / Sn;
            const float* pq = g_posq + p*Dn;
            const float* ff = g_f + (size_t)se*Dn;
            float s = 0.f;
            #pragma unroll
            for (int ni=0;ni<8;ni++){
                int col = n0 + wn*64 + ni*8 + 2*t;
                float2 q2 = *(const float2*)(pq + col);
                float2 f2 = *(const float2*)(ff + col);
                float a0 = acc[mi][ni][rp*2+0], a1 = acc[mi][ni][rp*2+1];
                s += tanha(a0 + q2.x)*f2.x + tanha(a1 + q2.y)*f2.y;
            }
            rsum[mi][rp] = s;
        }
    }
    #pragma unroll
    for (int o=1;o<4;o<<=1)
        #pragma unroll
        for (int mi=0;mi<2;mi++)
            #pragma unroll
            for (int rp=0;rp<2;rp++)
                rsum[mi][rp] += __shfl_xor_sync(0xffffffffu, rsum[mi][rp], o);
    if (t==0){
        #pragma unroll
        for (int mi=0;mi<2;mi++)
            #pragma unroll
            for (int rp=0;rp<2;rp++)
                atomicAdd(&g_mscal[ar0 + mi*16 + rp*8], rsum[mi][rp]);
    }
}

// ---------------- K8: sr per session + l2norm + fp16 pack ----------------
__global__ void k_sr(){
    __shared__ float sm[Sn];
    __shared__ float sred[8];
    __shared__ float srow[Dn];
    int b = blockIdx.x, t = threadIdx.x;
    if (t<Sn) sm[t] = g_mscal[b*Sn + t];
    __syncthreads();
    float acc = 0.f;
    #pragma unroll
    for (int s=0;s<Sn;s++) acc += g_h[(size_t)(b*Sn+s)*Dn + t]*sm[s];
    float ss = acc*acc;
    #pragma unroll
    for (int o=16;o;o>>=1) ss += __shfl_xor_sync(0xffffffffu, ss, o);
    if ((t&31)==0) sred[t>>5] = ss;
    __syncthreads();
    float tot = 0.f;
    #pragma unroll
    for (int w=0;w<8;w++) tot += sred[w];
    float val = acc / fmaxf(sqrtf(tot), 1e-12f);
    g_srn[(size_t)b*Dn + t] = val;
    srow[t] = val;
    __syncthreads();
    if (t < 64){
        int s = t;
        int c = s>>2, tq = s&3;
        int k0 = c*16 + 2*tq;
        unsigned short h0=hfr(srow[k0]),   h1=hfr(srow[k0+1]);
        unsigned short h2=hfr(srow[k0+8]), h3=hfr(srow[k0+9]);
        uint2 o;
        o.x = ((unsigned)h1<<16) | h0;
        o.y = ((unsigned)h3<<16) | h2;
        g_ap[b*64 + s] = o;
    }
}

// ---------------- K9: phi head + masked logits (merged) ----------------
__global__ void k_phimask(const float* __restrict__ sc1_w, const float* __restrict__ sc1_b,
                          const float* __restrict__ sc2_w,
                          const int* __restrict__ iid, const float* __restrict__ emb){
    if (blockIdx.x < Bn/8){
        __shared__ float ssr[8][Dn];
        __shared__ float s_p[8][2];
        int b0 = blockIdx.x*8;
        int t = threadIdx.x;
        for (int idx=t; idx<8*Dn; idx+=256){
            int j = idx>>8, k = idx&255;
            ssr[j][k] = g_srn[(size_t)(b0+j)*Dn + k];
        }
        if (t<16) s_p[t>>1][t&1] = 0.f;
        __syncthreads();
        float acc[8] = {0,0,0,0,0,0,0,0};
        int d = t;
        for (int k=0;k<Dn;k++){
            float w = sc1_w[(size_t)k*Dn + d];
            #pragma unroll
            for (int j=0;j<8;j++) acc[j] += ssr[j][k]*w;
        }
        float bb = sc1_b[d], w0 = sc2_w[d*2], w1 = sc2_w[d*2+1];
        int lane = t&31;
        #pragma unroll
        for (int j=0;j<8;j++){
            float hid = fmaxf(acc[j]+bb, 0.f);
            float p0 = hid*w0, p1 = hid*w1;
            #pragma unroll
            for (int o=16;o;o>>=1){
                p0 += __shfl_xor_sync(0xffffffffu, p0, o);
                p1 += __shfl_xor_sync(0xffffffffu, p1, o);
            }
            if (lane==0){ atomicAdd(&s_p[j][0], p0); atomicAdd(&s_p[j][1], p1); }
        }
        __syncthreads();
        if (t<8){
            float a0 = s_p[t][0], a1 = s_p[t][1];
            float m = fmaxf(a0,a1);
            float lse = m + logf(__expf(a0-m)+__expf(a1-m));
            g_logphi[(b0+t)*2+0] = a0 - lse;
            g_logphi[(b0+t)*2+1] = a1 - lse;
        }
    } else {
        __shared__ int iids[Sn];
        __shared__ float s_sr[Dn];
        int b = blockIdx.x - Bn/8;
        int t = threadIdx.x;
        if (t<Sn) iids[t] = iid[b*Sn+t];
        if (t<Dn) s_sr[t] = g_srn[(size_t)b*Dn + t];
        __syncthreads();
        int warp = t>>5, lane = t&31;
        for (int slot=warp; slot<Sn; slot+=8){
            int v = iids[slot];
            bool dup = false;
            for (int j=0;j<slot;j++) if (iids[j]==v) { dup=true; break; }
            if (dup){
                if (lane==0) g_mask_v[b*Sn+slot] = -1;
                continue;
            }
            const float* ev = emb + (size_t)v*Dn;
            float dot = 0.f;
            for (int k=lane;k<Dn;k+=32) dot += s_sr[k]*ev[k];
            #pragma unroll
            for (int o=16;o;o>>=1) dot += __shfl_xor_sync(0xffffffffu, dot, o);
            if (lane==0){
                float l = dot * g_inorm[v] * 12.f;
                g_mask_v[b*Sn+slot] = v;
                g_mask_l[b*Sn+slot] = l;
                atomicAdd(&g_msum[b], (double)__expf(l-SHIFT));
            }
        }
    }
}

// ---------------- K11: cp.async fp16 GEMM, f16-accum MMA (promote every 4 chunks) ----------------
// CTA 128M x 128N, 512 threads (16 warps 4x4), warp tile 32x32, 16 K-chunks, 4-stage ring.
#define NSTAGE 4
__global__ void __launch_bounds__(512,2) k_gemm_mma(){
    __shared__ __align__(16) uint2 sA[NSTAGE][128][4];
    __shared__ __align__(16) uint2 sB[NSTAGE][128][4];
    int tid = threadIdx.x;
    int w = tid>>5, lane = tid&31;
    int g = lane>>2, t = lane&3;
    int wm = w>>2, wn = w&3;           // 4 x 4 warps
    int m0 = blockIdx.x*128;
    int v0 = blockIdx.y*128;

    unsigned sAu = smem_u32(&sA[0][0][0]);
    unsigned sBu = smem_u32(&sB[0][0][0]);

    // staging: threads 0..255 -> A, 256..511 -> B; each 16B per chunk
    int mrow = (tid>>1)&127, shalf = tid&1;
    bool isB = (tid >= 256);
    int svrow = v0 + mrow;
    int cbytes = (!isB || svrow < Vn) ? 16 : 0;
    const uint2* csrc0 = isB ? (g_bp + (size_t)((svrow<Vn)?svrow:0)*64 + shalf*2)
                             : (g_ap + (m0+mrow)*64 + shalf*2);
    unsigned cdst0 = (isB ? sBu : sAu) + (unsigned)((mrow*4 + shalf*2)*8);

    float acc[2][4][4];
    #pragma unroll
    for (int mi=0;mi<2;mi++)
        #pragma unroll
        for (int ni=0;ni<4;ni++)
            #pragma unroll
            for (int q=0;q<4;q++) acc[mi][ni][q]=0.f;

    #pragma unroll
    for (int s=0;s<NSTAGE-1;s++){
        cp16(cdst0 + (unsigned)(s*4096), csrc0 + s*4, cbytes);
        CP_COMMIT();
    }

    unsigned hacc[2][4][2];
    #pragma unroll 4
    for (int c=0; c<16; c++){
        CP_WAIT2();
        __syncthreads();
        int cn = c + NSTAGE - 1;
        if (cn < 16){
            int sn = cn & (NSTAGE-1);
            cp16(cdst0 + (unsigned)(sn*4096), csrc0 + cn*4, cbytes);
        }
        CP_COMMIT();
        int st = c & (NSTAGE-1);
        if ((c & 3) == 0){
            #pragma unroll
            for (int mi=0;mi<2;mi++)
                #pragma unroll
                for (int ni=0;ni<4;ni++){ hacc[mi][ni][0]=0u; hacc[mi][ni][1]=0u; }
        }
        uint2 A0[2], A1[2], Bf[4];
        #pragma unroll
        for (int mi=0;mi<2;mi++){
            A0[mi] = sA[st][wm*32 + mi*16 + g][t];
            A1[mi] = sA[st][wm*32 + mi*16 + 8 + g][t];
        }
        #pragma unroll
        for (int ni=0;ni<4;ni++)
            Bf[ni] = sB[st][wn*32 + ni*8 + g][t];
        #pragma unroll
        for (int ni=0;ni<4;ni++){
            #pragma unroll
            for (int mi=0;mi<2;mi++){
                MMA_F16ACC(hacc[mi][ni][0], hacc[mi][ni][1],
                           A0[mi].x, A1[mi].x, A0[mi].y, A1[mi].y, Bf[ni].x, Bf[ni].y);
            }
        }
        if ((c & 3) == 3){
            #pragma unroll
            for (int mi=0;mi<2;mi++)
                #pragma unroll
                for (int ni=0;ni<4;ni++){
                    float2 f0 = __half22float2(*(__half2*)&hacc[mi][ni][0]);
                    float2 f1 = __half22float2(*(__half2*)&hacc[mi][ni][1]);
                    acc[mi][ni][0] += f0.x; acc[mi][ni][1] += f0.y;
                    acc[mi][ni][2] += f1.x; acc[mi][ni][3] += f1.y;
                }
        }
    }

    const float L2E = 1.44269504f;
    float rsum[4] = {0.f,0.f,0.f,0.f};
    #pragma unroll
    for (int mi=0;mi<2;mi++){
        int r0 = m0 + wm*32 + mi*16 + g;
        #pragma unroll
        for (int ni=0;ni<4;ni++){
            int col = v0 + wn*32 + ni*8 + 2*t;
            if (col < Vn){
                float s0 = 12.f*g_inorm[col], s1 = 12.f*g_inorm[col+1];
                float v00 = acc[mi][ni][0]*s0, v01 = acc[mi][ni][1]*s1;
                float v10 = acc[mi][ni][2]*s0, v11 = acc[mi][ni][3]*s1;
                __half2 h0 = __floats2half2_rn(v00, v01);
                __half2 h1 = __floats2half2_rn(v10, v11);
                unsigned* p0 = (unsigned*)(g_lt + (size_t)r0*Vn + col);
                unsigned* p1 = (unsigned*)(g_lt + (size_t)(r0+8)*Vn + col);
                *p0 = *(unsigned*)&h0;
                *p1 = *(unsigned*)&h1;
                rsum[mi*2+0] += exp2_pair_sum((v00-SHIFT)*L2E, (v01-SHIFT)*L2E);
                rsum[mi*2+1] += exp2_pair_sum((v10-SHIFT)*L2E, (v11-SHIFT)*L2E);
            }
        }
    }
    #pragma unroll
    for (int o=1;o<4;o<<=1)
        #pragma unroll
        for (int j=0;j<4;j++) rsum[j] += __shfl_xor_sync(0xffffffffu, rsum[j], o);
    if (t==0){
        #pragma unroll
        for (int j=0;j<4;j++){
            int row = m0 + wm*32 + (j>>1)*16 + (j&1)*8 + g;
            atomicAdd(&g_rowsum[row], (double)rsum[j]);
        }
    }
}

// ---------------- K12: shift + fp16->fp32 expand ----------------
__global__ void k_finalize(float* __restrict__ out){
    __shared__ float s_shift;
    int row = blockIdx.y;
    if (threadIdx.x==0){
        double sex = g_rowsum[row] - g_msum[row];
        s_shift = g_logphi[row*2+1] - (float)((double)SHIFT + log(sex));
    }
    __syncthreads();
    float sh = s_shift;
    int i = blockIdx.x*blockDim.x + threadIdx.x;
    if (i < Vn/8){
        const uint4* lp = (const uint4*)(g_lt + (size_t)row*Vn) + i;
        uint4 u = __ldcs(lp);
        __half2 a = *(__half2*)&u.x, b = *(__half2*)&u.y;
        __half2 cc = *(__half2*)&u.z, d = *(__half2*)&u.w;
        float2 fa = __half22float2(a), fb = __half22float2(b);
        float2 fc = __half22float2(cc), fd = __half22float2(d);
        float4* op = (float4*)(out + (size_t)row*Vn) + i*2;
        __stcs(op,   make_float4(fa.x+sh, fa.y+sh, fb.x+sh, fb.y+sh));
        __stcs(op+1, make_float4(fc.x+sh, fc.y+sh, fd.x+sh, fd.y+sh));
    }
}

// ---------------- K13: overwrite masked entries ----------------
__global__ void k_fixup(float* __restrict__ out){
    int b = blockIdx.x, s = threadIdx.x;
    if (s >= Sn) return;
    int v = g_mask_v[b*Sn+s];
    if (v < 0) return;
    float lse_in = (float)((double)SHIFT + log(g_msum[b]));
    out[(size_t)b*Vn + v] = g_mask_l[b*Sn+s] - lse_in + g_logphi[b*2+0];
}

// ---------------- launch ----------------
extern "C" void kernel_launch(void* const* d_in, const int* in_sizes, int n_in,
                              void* d_out, int out_size){
    const int* iid      = (const int*)d_in[0];
    const int* src      = (const int*)d_in[1];
    const int* dst      = (const int*)d_in[2];
    const int* dis      = (const int*)d_in[3];
    const int* tid_     = (const int*)d_in[7];
    const int* last_idx = (const int*)d_in[8];
    const float* emb        = (const float*)d_in[9];
    const float* pos_emb    = (const float*)d_in[10];
    const float* dis_emb    = (const float*)d_in[11];
    const float* target_emb = (const float*)d_in[12];
    const float* pi_w  = (const float*)d_in[13];
    const float* M_w   = (const float*)d_in[14];
    const float* q_w   = (const float*)d_in[15];
    const float* r_w   = (const float*)d_in[16];
    const float* sc1_w = (const float*)d_in[17];
    const float* sc1_b = (const float*)d_in[18];
    const float* sc2_w = (const float*)d_in[19];
    float* out = (float*)d_out;

    k_zero<<<(Nn+255)/256,256>>>();                      // 1
    k_count<<<En/256,256>>>(dst);                        // 2
    k_scan<<<1,1024>>>();                                // 3
    k_bpacknorm<<<Vn/8,256>>>(emb);                      // 4 (profiled slot)
    k_scatter<<<En/256,256>>>(dst);                      // 5
    int setup_blocks = (Nn*Dn)/256 + (Dn*64)/256 + Sn;
    k_setup<<<setup_blocks,256>>>(emb, iid, q_w, pos_emb); // 6
    k_gat<<<Nn,256>>>(src,dis,dis_emb,pi_w,M_w);         // 7
    k_f<<<Bn/8,256>>>(tid_,last_idx,target_emb,r_w);     // 8
    dim3 ge(Nn/128, 2);
    k_eagg_mma<<<ge,256>>>();                            // 9
    k_sr<<<Bn,256>>>();                                  // 10
    k_phimask<<<Bn/8 + Bn,256>>>(sc1_w,sc1_b,sc2_w,iid,emb); // 11
    dim3 gg(4, (Vn+127)/128);
    k_gemm_mma<<<gg, 512>>>();                           // 12
    dim3 gf((Vn/8 + 255)/256, Bn);
    k_finalize<<<gf,256>>>(out);                         // 13
    k_fixup<<<Bn,32>>>(out);                             // 14
}